// round 13
// baseline (speedup 1.0000x reference)
#include <cuda_runtime.h>
#include <cuda_fp16.h>
#include <math.h>
#include <stdint.h>

#define B   8
#define NG  5
#define NL  75
#define NF  196
#define C   640
#define NT  (NL*NF)
#define NMEAN_DEN (NG + NT)
#define INV_ALPHA 10.0f
#define L2EPS 1e-12f
#define NCHUNK 5

#define OFF_SG     0
#define OFF_SL     (OFF_SG + B*C)
#define OFF_GPROJ  (OFF_SL + B*C)
#define OFF_M1     (OFF_GPROJ + B*NG*C)
#define OFF_M2     (OFF_M1 + B*C)
#define OFF_MEAN   (OFF_M2 + B*C)
#define OFF_GHAT   (OFF_MEAN + B*C)
#define SCRATCH_FLOATS (OFF_GHAT + B*NG*C)

__device__ __align__(16) float g_scratch[SCRATCH_FLOATS];
__device__ __align__(16) __half g_lfh[(size_t)B * NT * C];     // 150.5 MB half copy
__device__ __align__(16) __half g_wkh[C * C];
__device__ __align__(16) float g_s2c[NCHUNK][B * NT];          // per-chunk |z|^2
__device__ __align__(16) float g_dtc[NCHUNK][B * NT * NG];     // per-chunk dots

// ---------------- helpers ----------------
__device__ __forceinline__ uint32_t smem_u32(const void* p) {
    uint32_t a;
    asm("{ .reg .u64 t; cvta.to.shared.u64 t, %1; cvt.u32.u64 %0, t; }" : "=r"(a) : "l"(p));
    return a;
}
__device__ __forceinline__ void cpa16(uint32_t dst, const void* src) {
    asm volatile("cp.async.cg.shared.global [%0], [%1], 16;" :: "r"(dst), "l"(src));
}
__device__ __forceinline__ void ldm_x4(uint32_t* r, uint32_t addr) {
    asm volatile("ldmatrix.sync.aligned.m8n8.x4.shared.b16 {%0,%1,%2,%3}, [%4];"
                 : "=r"(r[0]), "=r"(r[1]), "=r"(r[2]), "=r"(r[3]) : "r"(addr));
}
__device__ __forceinline__ void mma_f16(float* d, const uint32_t* a, const uint32_t* b) {
    asm volatile(
        "mma.sync.aligned.m16n8k16.row.col.f32.f16.f16.f32 "
        "{%0,%1,%2,%3}, {%4,%5,%6,%7}, {%8,%9}, {%0,%1,%2,%3};"
        : "+f"(d[0]), "+f"(d[1]), "+f"(d[2]), "+f"(d[3])
        : "r"(a[0]), "r"(a[1]), "r"(a[2]), "r"(a[3]), "r"(b[0]), "r"(b[1]));
}

// ---------------- small kernels ----------------
// merged: zero SL + convert Wk to half
__global__ void prep_k(const float* __restrict__ Wk) {
    int i = blockIdx.x * blockDim.x + threadIdx.x;
    if (i < B * C) g_scratch[OFF_SL + i] = 0.f;
    if (i < C * C) g_wkh[i] = __float2half_rn(Wk[i]);
}

__global__ void sum_global_k(const float* __restrict__ gf) {
    int b = blockIdx.x, c = threadIdx.x;  // blockDim=640
    float acc = 0.f;
#pragma unroll
    for (int g = 0; g < NG; g++) acc += gf[(b * NG + g) * C + c];
    g_scratch[OFF_SG + b * C + c] = acc;
}

// fused: SL column-sum + fp32->fp16 conversion; token loop unrolled x4 (MLP)
__global__ void convert_local_k(const float* __restrict__ lf) {
    int split = blockIdx.x, b = blockIdx.y, c = threadIdx.x;  // blockDim=640
    int per = (NT + gridDim.x - 1) / gridDim.x;
    int t0 = split * per, t1 = min(t0 + per, NT);
    const float* base = lf + ((size_t)b * NT) * C + c;
    __half* hbase = g_lfh + ((size_t)b * NT) * C + c;
    float acc = 0.f;
    int t = t0;
    for (; t + 4 <= t1; t += 4) {
        float v0 = base[(size_t)(t + 0) * C];
        float v1 = base[(size_t)(t + 1) * C];
        float v2 = base[(size_t)(t + 2) * C];
        float v3 = base[(size_t)(t + 3) * C];
        acc += v0 + v1 + v2 + v3;
        hbase[(size_t)(t + 0) * C] = __float2half_rn(v0);
        hbase[(size_t)(t + 1) * C] = __float2half_rn(v1);
        hbase[(size_t)(t + 2) * C] = __float2half_rn(v2);
        hbase[(size_t)(t + 3) * C] = __float2half_rn(v3);
    }
    for (; t < t1; ++t) {
        float v = base[(size_t)t * C];
        acc += v;
        hbase[(size_t)t * C] = __float2half_rn(v);
    }
    atomicAdd(&g_scratch[OFF_SL + b * C + c], acc);
}

// coalesced warp-per-row projection; grid (NG+2, B, 16), 256 thr (40 dims/block)
__global__ void proj_k(const float* __restrict__ gf,
                       const float* __restrict__ Wq,
                       const float* __restrict__ Wk) {
    int r = blockIdx.x, b = blockIdx.y, ds = blockIdx.z;
    __shared__ float xs[C];
    const float* x; const float* W; float* out;
    if (r < NG)       { x = gf + (b * NG + r) * C;      W = Wq; out = &g_scratch[OFF_GPROJ + (b * NG + r) * C]; }
    else if (r == NG) { x = &g_scratch[OFF_SG + b * C]; W = Wq; out = &g_scratch[OFF_M1 + b * C]; }
    else              { x = &g_scratch[OFF_SL + b * C]; W = Wk; out = &g_scratch[OFF_M2 + b * C]; }
    for (int c = threadIdx.x; c < C; c += blockDim.x) xs[c] = x[c];
    __syncthreads();
    int w = threadIdx.x >> 5, lane = threadIdx.x & 31;
    for (int d = ds * 40 + w; d < (ds + 1) * 40; d += 8) {
        const float* wr = W + (size_t)d * C;
        float a = 0.f;
        for (int c = lane; c < C; c += 32) a += wr[c] * xs[c];
#pragma unroll
        for (int o = 16; o; o >>= 1) a += __shfl_xor_sync(0xffffffffu, a, o);
        if (lane == 0) out[d] = a;
    }
}

__global__ void meanghat_k() {
    int b = blockIdx.x, c = threadIdx.x;  // blockDim=640
    __shared__ float red[32];
    float mean = (g_scratch[OFF_M1 + b * C + c] + g_scratch[OFF_M2 + b * C + c])
                 * (1.0f / (float)NMEAN_DEN);
    g_scratch[OFF_MEAN + b * C + c] = mean;
    for (int j = 0; j < NG; j++) {
        float v = g_scratch[OFF_GPROJ + (b * NG + j) * C + c] - mean;
        float s = v * v;
#pragma unroll
        for (int o = 16; o; o >>= 1) s += __shfl_xor_sync(0xffffffffu, s, o);
        if ((threadIdx.x & 31) == 0) red[threadIdx.x >> 5] = s;
        __syncthreads();
        if (threadIdx.x < 32) {
            float t = (threadIdx.x < 20) ? red[threadIdx.x] : 0.f;
#pragma unroll
            for (int o = 16; o; o >>= 1) t += __shfl_xor_sync(0xffffffffu, t, o);
            if (threadIdx.x == 0) red[0] = t;
        }
        __syncthreads();
        float inv = rsqrtf(red[0] + L2EPS);
        g_scratch[OFF_GHAT + (b * NG + j) * C + c] = v * inv;
        __syncthreads();
    }
}

// ---------------- fp16 GEMM (R11 config): 128x128x32, warp 64x32, 2 CTA/SM ----
#define BM 128
#define BN 128
#define BK 32
#define ROWH 40
#define STAGE_BYTES (2*BM*ROWH*2)        // 20480
#define STG 3
#define EG_BOFF (STG*STAGE_BYTES)        // 61440
#define RA_BOFF (EG_BOFF + 6*BN*4)       // 64512
#define GSMEM_BYTES (RA_BOFF + BM*6*4)   // 67584
#define KITER (C/BK)                     // 20

__device__ __forceinline__ void load_tile(int it, int stage, uint32_t sb,
                                          const __half* lfb,
                                          int t0, int d0, int tid) {
    uint32_t ab = sb + stage * STAGE_BYTES;
    uint32_t bb = ab + BM * ROWH * 2;
    int seg = tid & 3;
    int r0 = tid >> 2;
    int k0 = it * BK;
#pragma unroll
    for (int h = 0; h < 2; h++) {
        int row = r0 + h * 64;
        int tok = t0 + row; if (tok >= NT) tok = NT - 1;
        cpa16(ab + row * (ROWH * 2) + seg * 16, lfb + (size_t)tok * C + k0 + seg * 8);
        cpa16(bb + row * (ROWH * 2) + seg * 16, g_wkh + (size_t)(d0 + row) * C + k0 + seg * 8);
    }
    asm volatile("cp.async.commit_group;" ::: "memory");
}

__global__ __launch_bounds__(256, 2)
void gemm_mma_k() {
    extern __shared__ __align__(16) char smc[];
    uint32_t sb = smem_u32(smc);
    int tid = threadIdx.x, wid = tid >> 5, lane = tid & 31;
    int g = lane >> 2, t = lane & 3;
    int g8 = lane >> 3, lr = lane & 7;
    int wm = wid >> 2, wn = wid & 3;     // 2 x 4 warp grid
    int chunk = blockIdx.x, b = blockIdx.z;
    int t0 = blockIdx.y * BM;
    int d0 = chunk * BN;
    const __half* lfb = g_lfh + (size_t)b * NT * C;

    float acc[4][4][4];
#pragma unroll
    for (int mt = 0; mt < 4; mt++)
#pragma unroll
        for (int nt = 0; nt < 4; nt++)
#pragma unroll
            for (int cc = 0; cc < 4; cc++) acc[mt][nt][cc] = 0.f;

    load_tile(0, 0, sb, lfb, t0, d0, tid);
    load_tile(1, 1, sb, lfb, t0, d0, tid);

    int a_row = wm * 64 + (g8 & 1) * 8 + lr;
    int a_kc8 = (g8 >> 1) * 8;
    int b_row = wn * 32 + g8 * 8 + lr;

    for (int it = 0; it < KITER; it++) {
        int s = it % STG;
        if (it == KITER - 1) asm volatile("cp.async.wait_group 0;" ::: "memory");
        else                 asm volatile("cp.async.wait_group 1;" ::: "memory");
        __syncthreads();
        if (it + 2 < KITER) load_tile(it + 2, (it + 2) % STG, sb, lfb, t0, d0, tid);

        uint32_t as_ = sb + s * STAGE_BYTES;
        uint32_t bs_ = as_ + BM * ROWH * 2;
#pragma unroll
        for (int kk = 0; kk < 2; kk++) {
            int kb = kk * 16;
            uint32_t af[4][4], bt0[4], bt1[4];
#pragma unroll
            for (int mt = 0; mt < 4; mt++)
                ldm_x4(af[mt], as_ + ((a_row + mt * 16) * ROWH + kb + a_kc8) * 2);
            ldm_x4(bt0, bs_ + (b_row * ROWH + kb) * 2);
            ldm_x4(bt1, bs_ + (b_row * ROWH + kb + 8) * 2);
#pragma unroll
            for (int mt = 0; mt < 4; mt++)
#pragma unroll
                for (int nt = 0; nt < 4; nt++) {
                    uint32_t bf[2] = {bt0[nt], bt1[nt]};
                    mma_f16(acc[mt][nt], af[mt], bf);
                }
        }
        __syncthreads();
    }

    // ---- epilogue ----
    float* eg = (float*)(smc + EG_BOFF);   // eg[j][128]
    float* ra = (float*)(smc + RA_BOFF);   // rowacc[128][6]
    for (int idx = tid; idx < 6 * BN; idx += 256) {
        int j = idx >> 7, c = idx & 127;
        eg[idx] = (j < 5) ? g_scratch[OFF_GHAT + (b * NG + j) * C + d0 + c]
                          : g_scratch[OFF_MEAN + b * C + d0 + c];
    }
    for (int idx = tid; idx < BM * 6; idx += 256) ra[idx] = 0.f;
    __syncthreads();

#pragma unroll
    for (int mt = 0; mt < 4; mt++) {
#pragma unroll
        for (int rv = 0; rv < 2; rv++) {
            int row = wm * 64 + mt * 16 + g + rv * 8;
            float v[6] = {0.f, 0.f, 0.f, 0.f, 0.f, 0.f};
#pragma unroll
            for (int nt = 0; nt < 4; nt++) {
#pragma unroll
                for (int cc = 0; cc < 2; cc++) {
                    int col = wn * 32 + nt * 8 + 2 * t + cc;
                    float z = acc[mt][nt][rv * 2 + cc] - eg[5 * BN + col];
                    v[0] = fmaf(z, z, v[0]);
#pragma unroll
                    for (int j = 0; j < NG; j++)
                        v[1 + j] = fmaf(z, eg[j * BN + col], v[1 + j]);
                }
            }
#pragma unroll
            for (int j = 0; j < 6; j++) {
                v[j] += __shfl_xor_sync(0xffffffffu, v[j], 1);
                v[j] += __shfl_xor_sync(0xffffffffu, v[j], 2);
            }
            if (t == 0) {
#pragma unroll
                for (int j = 0; j < 6; j++) atomicAdd(&ra[row * 6 + j], v[j]);
            }
        }
    }
    __syncthreads();

    // plain per-chunk stores (no global atomics, no zeroing)
    for (int row = tid; row < BM; row += 256) {
        int tok = t0 + row;
        if (tok < NT) {
            g_s2c[chunk][b * NT + tok] = ra[row * 6];
            float* dp = &g_dtc[chunk][(b * NT + tok) * NG];
#pragma unroll
            for (int j = 0; j < NG; j++) dp[j] = ra[row * 6 + 1 + j];
        }
    }
}

// ---------------- softmax (sums the 5 chunk slices) ----------------
__global__ void softmax_k(float* __restrict__ out) {
    int j = blockIdx.x, l = blockIdx.y, b = blockIdx.z;
    int f = threadIdx.x;
    __shared__ float red[8];
    float s = -1e30f;
    if (f < NF) {
        int t = l * NF + f;
        float n2 = 0.f, d = 0.f;
#pragma unroll
        for (int ch = 0; ch < NCHUNK; ch++) {
            n2 += g_s2c[ch][b * NT + t];
            d  += g_dtc[ch][(b * NT + t) * NG + j];
        }
        s = d * rsqrtf(n2 + L2EPS) * INV_ALPHA;
    }
    float m = s;
#pragma unroll
    for (int o = 16; o; o >>= 1) m = fmaxf(m, __shfl_xor_sync(0xffffffffu, m, o));
    if ((threadIdx.x & 31) == 0) red[threadIdx.x >> 5] = m;
    __syncthreads();
    m = red[0];
#pragma unroll
    for (int w = 1; w < 8; w++) m = fmaxf(m, red[w]);
    float e = (f < NF) ? expf(s - m) : 0.f;
    float sum = e;
#pragma unroll
    for (int o = 16; o; o >>= 1) sum += __shfl_xor_sync(0xffffffffu, sum, o);
    __syncthreads();
    if ((threadIdx.x & 31) == 0) red[threadIdx.x >> 5] = sum;
    __syncthreads();
    sum = 0.f;
#pragma unroll
    for (int w = 0; w < 8; w++) sum += red[w];
    if (f < NF)
        out[(((size_t)b * NL + l) * NG + j) * NF + f] = e / sum;
}

// ---------------------------------------------------------------------------
extern "C" void kernel_launch(void* const* d_in, const int* in_sizes, int n_in,
                              void* d_out, int out_size) {
    const float* gf = (const float*)d_in[0];
    const float* lf = (const float*)d_in[1];
    const float* Wq = (const float*)d_in[2];
    const float* Wk = (const float*)d_in[3];
    float* out = (float*)d_out;

    cudaFuncSetAttribute(gemm_mma_k, cudaFuncAttributeMaxDynamicSharedMemorySize,
                         GSMEM_BYTES);

    prep_k<<<(C * C + 255) / 256, 256>>>(Wk);
    sum_global_k<<<B, C>>>(gf);
    convert_local_k<<<dim3(120, B), C>>>(lf);
    proj_k<<<dim3(NG + 2, B, 16), 256>>>(gf, Wq, Wk);
    meanghat_k<<<B, C>>>();
    gemm_mma_k<<<dim3(NCHUNK, (NT + BM - 1) / BM, B), 256, GSMEM_BYTES>>>();
    softmax_k<<<dim3(NG, NL, B), 256>>>(out);
}

// round 14
// speedup vs baseline: 1.5340x; 1.5340x over previous
#include <cuda_runtime.h>
#include <cuda_fp16.h>
#include <math.h>
#include <stdint.h>

#define B   8
#define NG  5
#define NL  75
#define NF  196
#define C   640
#define NT  (NL*NF)
#define NMEAN_DEN (NG + NT)
#define INV_ALPHA 10.0f
#define L2EPS 1e-12f

#define OFF_SG     0
#define OFF_SL     (OFF_SG + B*C)
#define OFF_GPROJ  (OFF_SL + B*C)
#define OFF_M1     (OFF_GPROJ + B*NG*C)
#define OFF_M2     (OFF_M1 + B*C)
#define OFF_MEAN   (OFF_M2 + B*C)
#define OFF_GHAT   (OFF_MEAN + B*C)
#define OFF_NORM2  (OFF_GHAT + B*NG*C)
#define OFF_DOTS   (OFF_NORM2 + B*NT)
#define SCRATCH_FLOATS (OFF_DOTS + B*NT*NG)

__device__ __align__(16) float g_scratch[SCRATCH_FLOATS];
__device__ __align__(16) __half g_lfh[(size_t)B * NT * C];   // 150.5 MB half copy
__device__ __align__(16) __half g_wkh[C * C];

// ---------------- helpers ----------------
__device__ __forceinline__ uint32_t smem_u32(const void* p) {
    uint32_t a;
    asm("{ .reg .u64 t; cvta.to.shared.u64 t, %1; cvt.u32.u64 %0, t; }" : "=r"(a) : "l"(p));
    return a;
}
__device__ __forceinline__ void cpa16(uint32_t dst, const void* src) {
    asm volatile("cp.async.cg.shared.global [%0], [%1], 16;" :: "r"(dst), "l"(src));
}
__device__ __forceinline__ void ldm_x4(uint32_t* r, uint32_t addr) {
    asm volatile("ldmatrix.sync.aligned.m8n8.x4.shared.b16 {%0,%1,%2,%3}, [%4];"
                 : "=r"(r[0]), "=r"(r[1]), "=r"(r[2]), "=r"(r[3]) : "r"(addr));
}
__device__ __forceinline__ void mma_f16(float* d, const uint32_t* a, const uint32_t* b) {
    asm volatile(
        "mma.sync.aligned.m16n8k16.row.col.f32.f16.f16.f32 "
        "{%0,%1,%2,%3}, {%4,%5,%6,%7}, {%8,%9}, {%0,%1,%2,%3};"
        : "+f"(d[0]), "+f"(d[1]), "+f"(d[2]), "+f"(d[3])
        : "r"(a[0]), "r"(a[1]), "r"(a[2]), "r"(a[3]), "r"(b[0]), "r"(b[1]));
}

// ---------------- small kernels ----------------
__global__ void zero_k() {
    int i = blockIdx.x * blockDim.x + threadIdx.x;
    if (i < B * C) g_scratch[OFF_SL + i] = 0.f;
    if (i < B * NT * (1 + NG)) g_scratch[OFF_NORM2 + i] = 0.f;
}

__global__ void sum_global_k(const float* __restrict__ gf) {
    int b = blockIdx.x, c = threadIdx.x;  // blockDim=640
    float acc = 0.f;
#pragma unroll
    for (int g = 0; g < NG; g++) acc += gf[(b * NG + g) * C + c];
    g_scratch[OFF_SG + b * C + c] = acc;
}

// fused: SL column-sum + fp32->fp16 conversion of local_f
__global__ void convert_local_k(const float* __restrict__ lf) {
    int split = blockIdx.x, b = blockIdx.y, c = threadIdx.x;  // blockDim=640
    int per = (NT + gridDim.x - 1) / gridDim.x;
    int t0 = split * per, t1 = min(t0 + per, NT);
    const float* base = lf + ((size_t)b * NT) * C + c;
    __half* hbase = g_lfh + ((size_t)b * NT) * C + c;
    float acc = 0.f;
    for (int t = t0; t < t1; ++t) {
        float v = base[(size_t)t * C];
        acc += v;
        hbase[(size_t)t * C] = __float2half_rn(v);
    }
    atomicAdd(&g_scratch[OFF_SL + b * C + c], acc);
}

__global__ void convert_wk_k(const float* __restrict__ Wk) {
    int i = blockIdx.x * blockDim.x + threadIdx.x;
    if (i < C * C) g_wkh[i] = __float2half_rn(Wk[i]);
}

// coalesced warp-per-row projection; grid (NG+2, B, 16), 256 thr (40 dims/block)
__global__ void proj_k(const float* __restrict__ gf,
                       const float* __restrict__ Wq,
                       const float* __restrict__ Wk) {
    int r = blockIdx.x, b = blockIdx.y, ds = blockIdx.z;
    __shared__ float xs[C];
    const float* x; const float* W; float* out;
    if (r < NG)       { x = gf + (b * NG + r) * C;      W = Wq; out = &g_scratch[OFF_GPROJ + (b * NG + r) * C]; }
    else if (r == NG) { x = &g_scratch[OFF_SG + b * C]; W = Wq; out = &g_scratch[OFF_M1 + b * C]; }
    else              { x = &g_scratch[OFF_SL + b * C]; W = Wk; out = &g_scratch[OFF_M2 + b * C]; }
    for (int c = threadIdx.x; c < C; c += blockDim.x) xs[c] = x[c];
    __syncthreads();
    int w = threadIdx.x >> 5, lane = threadIdx.x & 31;
    for (int d = ds * 40 + w; d < (ds + 1) * 40; d += 8) {
        const float* wr = W + (size_t)d * C;
        float a = 0.f;
        for (int c = lane; c < C; c += 32) a += wr[c] * xs[c];
#pragma unroll
        for (int o = 16; o; o >>= 1) a += __shfl_xor_sync(0xffffffffu, a, o);
        if (lane == 0) out[d] = a;
    }
}

__global__ void meanghat_k() {
    int b = blockIdx.x, c = threadIdx.x;  // blockDim=640
    __shared__ float red[32];
    float mean = (g_scratch[OFF_M1 + b * C + c] + g_scratch[OFF_M2 + b * C + c])
                 * (1.0f / (float)NMEAN_DEN);
    g_scratch[OFF_MEAN + b * C + c] = mean;
    for (int j = 0; j < NG; j++) {
        float v = g_scratch[OFF_GPROJ + (b * NG + j) * C + c] - mean;
        float s = v * v;
#pragma unroll
        for (int o = 16; o; o >>= 1) s += __shfl_xor_sync(0xffffffffu, s, o);
        if ((threadIdx.x & 31) == 0) red[threadIdx.x >> 5] = s;
        __syncthreads();
        if (threadIdx.x < 32) {
            float t = (threadIdx.x < 20) ? red[threadIdx.x] : 0.f;
#pragma unroll
            for (int o = 16; o; o >>= 1) t += __shfl_xor_sync(0xffffffffu, t, o);
            if (threadIdx.x == 0) red[0] = t;
        }
        __syncthreads();
        float inv = rsqrtf(red[0] + L2EPS);
        g_scratch[OFF_GHAT + (b * NG + j) * C + c] = v * inv;
        __syncthreads();
    }
}

// ---------------- fp16 GEMM: half smem + ldmatrix, BK=32 (R11 config) ----------
// Tile 128x128x32; 8 warps (2x4), warp tile 64x32.
// smem half rows: [row][40 halfs] (80B stride) -> conflict-free ldmatrix.
#define BM 128
#define BN 128
#define BK 32
#define ROWH 40
#define STAGE_BYTES (2*BM*ROWH*2)        // 20480
#define STG 3
#define EG_BOFF (STG*STAGE_BYTES)        // 61440
#define RA_BOFF (EG_BOFF + 6*BN*4)       // 64512
#define GSMEM_BYTES (RA_BOFF + BM*6*4)   // 67584
#define KITER (C/BK)                     // 20

__device__ __forceinline__ void load_tile(int it, int stage, uint32_t sb,
                                          const __half* lfb, const __half* wkb,
                                          int t0, int d0, int tid) {
    uint32_t ab = sb + stage * STAGE_BYTES;
    uint32_t bb = ab + BM * ROWH * 2;
    int seg = tid & 3;            // 16B chunk within 64B data row
    int r0 = tid >> 2;            // 0..63
    int k0 = it * BK;
#pragma unroll
    for (int h = 0; h < 2; h++) {
        int row = r0 + h * 64;
        int tok = t0 + row; if (tok >= NT) tok = NT - 1;
        cpa16(ab + row * (ROWH * 2) + seg * 16, lfb + (size_t)tok * C + k0 + seg * 8);
        cpa16(bb + row * (ROWH * 2) + seg * 16, wkb + (size_t)(d0 + row) * C + k0 + seg * 8);
    }
    asm volatile("cp.async.commit_group;" ::: "memory");
}

__global__ __launch_bounds__(256, 2)
void gemm_mma_k() {
    extern __shared__ __align__(16) char smc[];
    uint32_t sb = smem_u32(smc);
    int tid = threadIdx.x, wid = tid >> 5, lane = tid & 31;
    int g = lane >> 2, t = lane & 3;
    int g8 = lane >> 3, lr = lane & 7;   // ldmatrix address groups
    int wm = wid >> 2, wn = wid & 3;     // 2 x 4 warp grid
    int chunk = blockIdx.x, b = blockIdx.z;
    int t0 = blockIdx.y * BM;
    int d0 = chunk * BN;
    const __half* lfb = g_lfh + (size_t)b * NT * C;

    float acc[4][4][4];
#pragma unroll
    for (int mt = 0; mt < 4; mt++)
#pragma unroll
        for (int nt = 0; nt < 4; nt++)
#pragma unroll
            for (int cc = 0; cc < 4; cc++) acc[mt][nt][cc] = 0.f;

    load_tile(0, 0, sb, lfb, g_wkh, t0, d0, tid);
    load_tile(1, 1, sb, lfb, g_wkh, t0, d0, tid);

    // per-lane ldmatrix row offsets (within warp tile)
    int a_row = wm * 64 + (g8 & 1) * 8 + lr;     // + mt*16 ; kcol = (g8>>1)*8
    int a_kc8 = (g8 >> 1) * 8;
    int b_row = wn * 32 + g8 * 8 + lr;           // all 4 n8-tiles; kcol per load

    for (int it = 0; it < KITER; it++) {
        int s = it % STG;
        if (it == KITER - 1) asm volatile("cp.async.wait_group 0;" ::: "memory");
        else                 asm volatile("cp.async.wait_group 1;" ::: "memory");
        __syncthreads();
        if (it + 2 < KITER) load_tile(it + 2, (it + 2) % STG, sb, lfb, g_wkh, t0, d0, tid);

        uint32_t as_ = sb + s * STAGE_BYTES;
        uint32_t bs_ = as_ + BM * ROWH * 2;
#pragma unroll
        for (int kk = 0; kk < 2; kk++) {
            int kb = kk * 16;
            uint32_t af[4][4], bt0[4], bt1[4];
#pragma unroll
            for (int mt = 0; mt < 4; mt++)
                ldm_x4(af[mt], as_ + ((a_row + mt * 16) * ROWH + kb + a_kc8) * 2);
            ldm_x4(bt0, bs_ + (b_row * ROWH + kb) * 2);      // b0: k0-7 of 4 n8 tiles
            ldm_x4(bt1, bs_ + (b_row * ROWH + kb + 8) * 2);  // b1: k8-15
#pragma unroll
            for (int mt = 0; mt < 4; mt++)
#pragma unroll
                for (int nt = 0; nt < 4; nt++) {
                    uint32_t bf[2] = {bt0[nt], bt1[nt]};
                    mma_f16(acc[mt][nt], af[mt], bf);
                }
        }
        __syncthreads();
    }

    // ---- epilogue (same D layout) ----
    float* eg = (float*)(smc + EG_BOFF);   // eg[j][128], j=0..4 ghat, j=5 mean
    float* ra = (float*)(smc + RA_BOFF);   // rowacc[128][6]
    for (int idx = tid; idx < 6 * BN; idx += 256) {
        int j = idx >> 7, c = idx & 127;
        eg[idx] = (j < 5) ? g_scratch[OFF_GHAT + (b * NG + j) * C + d0 + c]
                          : g_scratch[OFF_MEAN + b * C + d0 + c];
    }
    for (int idx = tid; idx < BM * 6; idx += 256) ra[idx] = 0.f;
    __syncthreads();

#pragma unroll
    for (int mt = 0; mt < 4; mt++) {
#pragma unroll
        for (int rv = 0; rv < 2; rv++) {
            int row = wm * 64 + mt * 16 + g + rv * 8;
            float v[6] = {0.f, 0.f, 0.f, 0.f, 0.f, 0.f};
#pragma unroll
            for (int nt = 0; nt < 4; nt++) {
#pragma unroll
                for (int cc = 0; cc < 2; cc++) {
                    int col = wn * 32 + nt * 8 + 2 * t + cc;
                    float z = acc[mt][nt][rv * 2 + cc] - eg[5 * BN + col];
                    v[0] = fmaf(z, z, v[0]);
#pragma unroll
                    for (int j = 0; j < NG; j++)
                        v[1 + j] = fmaf(z, eg[j * BN + col], v[1 + j]);
                }
            }
#pragma unroll
            for (int j = 0; j < 6; j++) {
                v[j] += __shfl_xor_sync(0xffffffffu, v[j], 1);
                v[j] += __shfl_xor_sync(0xffffffffu, v[j], 2);
            }
            if (t == 0) {
#pragma unroll
                for (int j = 0; j < 6; j++) atomicAdd(&ra[row * 6 + j], v[j]);
            }
        }
    }
    __syncthreads();

    for (int row = tid; row < BM; row += 256) {
        int tok = t0 + row;
        if (tok < NT) {
            atomicAdd(&g_scratch[OFF_NORM2 + b * NT + tok], ra[row * 6]);
            float* dp = &g_scratch[OFF_DOTS + ((size_t)b * NT + tok) * NG];
#pragma unroll
            for (int j = 0; j < NG; j++) atomicAdd(dp + j, ra[row * 6 + 1 + j]);
        }
    }
}

// ---------------- softmax ----------------
__global__ void softmax_k(float* __restrict__ out) {
    int j = blockIdx.x, l = blockIdx.y, b = blockIdx.z;
    int f = threadIdx.x;
    __shared__ float red[8];
    float s = -1e30f;
    if (f < NF) {
        int t = l * NF + f;
        float n2 = g_scratch[OFF_NORM2 + b * NT + t];
        float d  = g_scratch[OFF_DOTS + ((size_t)b * NT + t) * NG + j];
        s = d * rsqrtf(n2 + L2EPS) * INV_ALPHA;
    }
    float m = s;
#pragma unroll
    for (int o = 16; o; o >>= 1) m = fmaxf(m, __shfl_xor_sync(0xffffffffu, m, o));
    if ((threadIdx.x & 31) == 0) red[threadIdx.x >> 5] = m;
    __syncthreads();
    m = red[0];
#pragma unroll
    for (int w = 1; w < 8; w++) m = fmaxf(m, red[w]);
    float e = (f < NF) ? expf(s - m) : 0.f;
    float sum = e;
#pragma unroll
    for (int o = 16; o; o >>= 1) sum += __shfl_xor_sync(0xffffffffu, sum, o);
    __syncthreads();
    if ((threadIdx.x & 31) == 0) red[threadIdx.x >> 5] = sum;
    __syncthreads();
    sum = 0.f;
#pragma unroll
    for (int w = 0; w < 8; w++) sum += red[w];
    if (f < NF)
        out[(((size_t)b * NL + l) * NG + j) * NF + f] = e / sum;
}

// ---------------------------------------------------------------------------
extern "C" void kernel_launch(void* const* d_in, const int* in_sizes, int n_in,
                              void* d_out, int out_size) {
    const float* gf = (const float*)d_in[0];
    const float* lf = (const float*)d_in[1];
    const float* Wq = (const float*)d_in[2];
    const float* Wk = (const float*)d_in[3];
    float* out = (float*)d_out;

    cudaFuncSetAttribute(gemm_mma_k, cudaFuncAttributeMaxDynamicSharedMemorySize,
                         GSMEM_BYTES);

    zero_k<<<(B * NT * (1 + NG) + 255) / 256, 256>>>();
    sum_global_k<<<B, C>>>(gf);
    convert_local_k<<<dim3(120, B), C>>>(lf);
    convert_wk_k<<<(C * C + 255) / 256, 256>>>(Wk);
    proj_k<<<dim3(NG + 2, B, 16), 256>>>(gf, Wq, Wk);
    meanghat_k<<<B, C>>>();
    gemm_mma_k<<<dim3(C / BN, (NT + BM - 1) / BM, B), 256, GSMEM_BYTES>>>();
    softmax_k<<<dim3(NG, NL, B), 256>>>(out);
}

// round 15
// speedup vs baseline: 1.5600x; 1.0169x over previous
#include <cuda_runtime.h>
#include <cuda_fp16.h>
#include <math.h>
#include <stdint.h>

#define B   8
#define NG  5
#define NL  75
#define NF  196
#define C   640
#define NT  (NL*NF)
#define NMEAN_DEN (NG + NT)
#define INV_ALPHA 10.0f
#define L2EPS 1e-12f

#define OFF_SG     0
#define OFF_SL     (OFF_SG + B*C)
#define OFF_GPROJ  (OFF_SL + B*C)
#define OFF_M1     (OFF_GPROJ + B*NG*C)
#define OFF_M2     (OFF_M1 + B*C)
#define OFF_MEAN   (OFF_M2 + B*C)
#define OFF_GHAT   (OFF_MEAN + B*C)
#define OFF_NORM2  (OFF_GHAT + B*NG*C)
#define OFF_DOTS   (OFF_NORM2 + B*NT)
#define SCRATCH_FLOATS (OFF_DOTS + B*NT*NG)

__device__ __align__(16) float g_scratch[SCRATCH_FLOATS];
__device__ __align__(16) __half g_lfh[(size_t)B * NT * C];   // 150.5 MB half copy
__device__ __align__(16) __half g_wkh[C * C];

// ---------------- helpers ----------------
__device__ __forceinline__ uint32_t smem_u32(const void* p) {
    uint32_t a;
    asm("{ .reg .u64 t; cvta.to.shared.u64 t, %1; cvt.u32.u64 %0, t; }" : "=r"(a) : "l"(p));
    return a;
}
__device__ __forceinline__ void cpa16(uint32_t dst, const void* src) {
    asm volatile("cp.async.cg.shared.global [%0], [%1], 16;" :: "r"(dst), "l"(src));
}
__device__ __forceinline__ void ldm_x4(uint32_t* r, uint32_t addr) {
    asm volatile("ldmatrix.sync.aligned.m8n8.x4.shared.b16 {%0,%1,%2,%3}, [%4];"
                 : "=r"(r[0]), "=r"(r[1]), "=r"(r[2]), "=r"(r[3]) : "r"(addr));
}
__device__ __forceinline__ void mma_f16(float* d, const uint32_t* a, const uint32_t* b) {
    asm volatile(
        "mma.sync.aligned.m16n8k16.row.col.f32.f16.f16.f32 "
        "{%0,%1,%2,%3}, {%4,%5,%6,%7}, {%8,%9}, {%0,%1,%2,%3};"
        : "+f"(d[0]), "+f"(d[1]), "+f"(d[2]), "+f"(d[3])
        : "r"(a[0]), "r"(a[1]), "r"(a[2]), "r"(a[3]), "r"(b[0]), "r"(b[1]));
}

// ---------------- merged prep: zero SL/NORM2/DOTS + sum_global + convert Wk ----
__global__ void prep_k(const float* __restrict__ gf, const float* __restrict__ Wk) {
    int i = blockIdx.x * blockDim.x + threadIdx.x;
    if (i < B * C) {
        g_scratch[OFF_SL + i] = 0.f;
        int b = i / C, c = i - b * C;
        float acc = 0.f;
#pragma unroll
        for (int g = 0; g < NG; g++) acc += gf[(b * NG + g) * C + c];
        g_scratch[OFF_SG + i] = acc;
    }
    if (i < C * C) g_wkh[i] = __float2half_rn(Wk[i]);
    if (i < B * NT * (1 + NG)) g_scratch[OFF_NORM2 + i] = 0.f;
}

// fused: SL column-sum + fp32->fp16 conversion of local_f
__global__ void convert_local_k(const float* __restrict__ lf) {
    int split = blockIdx.x, b = blockIdx.y, c = threadIdx.x;  // blockDim=640
    int per = (NT + gridDim.x - 1) / gridDim.x;
    int t0 = split * per, t1 = min(t0 + per, NT);
    const float* base = lf + ((size_t)b * NT) * C + c;
    __half* hbase = g_lfh + ((size_t)b * NT) * C + c;
    float acc = 0.f;
    for (int t = t0; t < t1; ++t) {
        float v = base[(size_t)t * C];
        acc += v;
        hbase[(size_t)t * C] = __float2half_rn(v);
    }
    atomicAdd(&g_scratch[OFF_SL + b * C + c], acc);
}

// coalesced warp-per-row projection; grid (NG+2, B, 16), 256 thr (40 dims/block)
__global__ void proj_k(const float* __restrict__ gf,
                       const float* __restrict__ Wq,
                       const float* __restrict__ Wk) {
    int r = blockIdx.x, b = blockIdx.y, ds = blockIdx.z;
    __shared__ float xs[C];
    const float* x; const float* W; float* out;
    if (r < NG)       { x = gf + (b * NG + r) * C;      W = Wq; out = &g_scratch[OFF_GPROJ + (b * NG + r) * C]; }
    else if (r == NG) { x = &g_scratch[OFF_SG + b * C]; W = Wq; out = &g_scratch[OFF_M1 + b * C]; }
    else              { x = &g_scratch[OFF_SL + b * C]; W = Wk; out = &g_scratch[OFF_M2 + b * C]; }
    for (int c = threadIdx.x; c < C; c += blockDim.x) xs[c] = x[c];
    __syncthreads();
    int w = threadIdx.x >> 5, lane = threadIdx.x & 31;
    for (int d = ds * 40 + w; d < (ds + 1) * 40; d += 8) {
        const float* wr = W + (size_t)d * C;
        float a = 0.f;
        for (int c = lane; c < C; c += 32) a += wr[c] * xs[c];
#pragma unroll
        for (int o = 16; o; o >>= 1) a += __shfl_xor_sync(0xffffffffu, a, o);
        if (lane == 0) out[d] = a;
    }
}

__global__ void meanghat_k() {
    int b = blockIdx.x, c = threadIdx.x;  // blockDim=640
    __shared__ float red[32];
    float mean = (g_scratch[OFF_M1 + b * C + c] + g_scratch[OFF_M2 + b * C + c])
                 * (1.0f / (float)NMEAN_DEN);
    g_scratch[OFF_MEAN + b * C + c] = mean;
    for (int j = 0; j < NG; j++) {
        float v = g_scratch[OFF_GPROJ + (b * NG + j) * C + c] - mean;
        float s = v * v;
#pragma unroll
        for (int o = 16; o; o >>= 1) s += __shfl_xor_sync(0xffffffffu, s, o);
        if ((threadIdx.x & 31) == 0) red[threadIdx.x >> 5] = s;
        __syncthreads();
        if (threadIdx.x < 32) {
            float t = (threadIdx.x < 20) ? red[threadIdx.x] : 0.f;
#pragma unroll
            for (int o = 16; o; o >>= 1) t += __shfl_xor_sync(0xffffffffu, t, o);
            if (threadIdx.x == 0) red[0] = t;
        }
        __syncthreads();
        float inv = rsqrtf(red[0] + L2EPS);
        g_scratch[OFF_GHAT + (b * NG + j) * C + c] = v * inv;
        __syncthreads();
    }
}

// ---------------- fp16 GEMM: 128x128x64, 2-stage double buffer ----------------
// 8 warps (2x4), warp tile 64x32. smem rows [row][72 halfs] (144B stride):
// ldmatrix row offsets lr*36 words mod 32 = {0,4,...,28} -> conflict-free.
#define BM 128
#define BN 128
#define BK 64
#define ROWH 72
#define STAGE_BYTES (2*BM*ROWH*2)        // 36864
#define STG 2
#define EG_BOFF (STG*STAGE_BYTES)        // 73728
#define RA_BOFF (EG_BOFF + 6*BN*4)       // 76800
#define GSMEM_BYTES (RA_BOFF + BM*6*4)   // 79872
#define KITER (C/BK)                     // 10

__device__ __forceinline__ void load_tile(int it, int stage, uint32_t sb,
                                          const __half* lfb, const __half* wkb,
                                          int t0, int d0, int tid) {
    uint32_t ab = sb + stage * STAGE_BYTES;
    uint32_t bb = ab + BM * ROWH * 2;
    int seg = tid & 7;            // 16B chunk within 128B data row
    int r0 = tid >> 3;            // 0..31
    int k0 = it * BK;
#pragma unroll
    for (int h = 0; h < 4; h++) {
        int row = r0 + h * 32;
        int tok = t0 + row; if (tok >= NT) tok = NT - 1;
        cpa16(ab + row * (ROWH * 2) + seg * 16, lfb + (size_t)tok * C + k0 + seg * 8);
        cpa16(bb + row * (ROWH * 2) + seg * 16, wkb + (size_t)(d0 + row) * C + k0 + seg * 8);
    }
    asm volatile("cp.async.commit_group;" ::: "memory");
}

__global__ __launch_bounds__(256, 2)
void gemm_mma_k() {
    extern __shared__ __align__(16) char smc[];
    uint32_t sb = smem_u32(smc);
    int tid = threadIdx.x, wid = tid >> 5, lane = tid & 31;
    int g = lane >> 2, t = lane & 3;
    int g8 = lane >> 3, lr = lane & 7;   // ldmatrix address groups
    int wm = wid >> 2, wn = wid & 3;     // 2 x 4 warp grid
    int chunk = blockIdx.x, b = blockIdx.z;
    int t0 = blockIdx.y * BM;
    int d0 = chunk * BN;
    const __half* lfb = g_lfh + (size_t)b * NT * C;

    float acc[4][4][4];
#pragma unroll
    for (int mt = 0; mt < 4; mt++)
#pragma unroll
        for (int nt = 0; nt < 4; nt++)
#pragma unroll
            for (int cc = 0; cc < 4; cc++) acc[mt][nt][cc] = 0.f;

    load_tile(0, 0, sb, lfb, g_wkh, t0, d0, tid);
    load_tile(1, 1, sb, lfb, g_wkh, t0, d0, tid);

    int a_row = wm * 64 + (g8 & 1) * 8 + lr;     // + mt*16 ; kcol = (g8>>1)*8
    int a_kc8 = (g8 >> 1) * 8;
    int b_row = wn * 32 + g8 * 8 + lr;           // all 4 n8-tiles

    for (int it = 0; it < KITER; it++) {
        int s = it & 1;
        if (it == KITER - 1) asm volatile("cp.async.wait_group 0;" ::: "memory");
        else                 asm volatile("cp.async.wait_group 1;" ::: "memory");
        __syncthreads();

        uint32_t as_ = sb + s * STAGE_BYTES;
        uint32_t bs_ = as_ + BM * ROWH * 2;
#pragma unroll
        for (int kk = 0; kk < 4; kk++) {
            int kb = kk * 16;
            uint32_t af[4][4], bt0[4], bt1[4];
#pragma unroll
            for (int mt = 0; mt < 4; mt++)
                ldm_x4(af[mt], as_ + ((a_row + mt * 16) * ROWH + kb + a_kc8) * 2);
            ldm_x4(bt0, bs_ + (b_row * ROWH + kb) * 2);
            ldm_x4(bt1, bs_ + (b_row * ROWH + kb + 8) * 2);
#pragma unroll
            for (int mt = 0; mt < 4; mt++)
#pragma unroll
                for (int nt = 0; nt < 4; nt++) {
                    uint32_t bf[2] = {bt0[nt], bt1[nt]};
                    mma_f16(acc[mt][nt], af[mt], bf);
                }
        }
        __syncthreads();
        if (it + 2 < KITER) load_tile(it + 2, s, sb, lfb, g_wkh, t0, d0, tid);
    }

    // ---- epilogue (same D layout) ----
    float* eg = (float*)(smc + EG_BOFF);   // eg[j][128], j=0..4 ghat, j=5 mean
    float* ra = (float*)(smc + RA_BOFF);   // rowacc[128][6]
    for (int idx = tid; idx < 6 * BN; idx += 256) {
        int j = idx >> 7, c = idx & 127;
        eg[idx] = (j < 5) ? g_scratch[OFF_GHAT + (b * NG + j) * C + d0 + c]
                          : g_scratch[OFF_MEAN + b * C + d0 + c];
    }
    for (int idx = tid; idx < BM * 6; idx += 256) ra[idx] = 0.f;
    __syncthreads();

#pragma unroll
    for (int mt = 0; mt < 4; mt++) {
#pragma unroll
        for (int rv = 0; rv < 2; rv++) {
            int row = wm * 64 + mt * 16 + g + rv * 8;
            float v[6] = {0.f, 0.f, 0.f, 0.f, 0.f, 0.f};
#pragma unroll
            for (int nt = 0; nt < 4; nt++) {
#pragma unroll
                for (int cc = 0; cc < 2; cc++) {
                    int col = wn * 32 + nt * 8 + 2 * t + cc;
                    float z = acc[mt][nt][rv * 2 + cc] - eg[5 * BN + col];
                    v[0] = fmaf(z, z, v[0]);
#pragma unroll
                    for (int j = 0; j < NG; j++)
                        v[1 + j] = fmaf(z, eg[j * BN + col], v[1 + j]);
                }
            }
#pragma unroll
            for (int j = 0; j < 6; j++) {
                v[j] += __shfl_xor_sync(0xffffffffu, v[j], 1);
                v[j] += __shfl_xor_sync(0xffffffffu, v[j], 2);
            }
            if (t == 0) {
#pragma unroll
                for (int j = 0; j < 6; j++) atomicAdd(&ra[row * 6 + j], v[j]);
            }
        }
    }
    __syncthreads();

    for (int row = tid; row < BM; row += 256) {
        int tok = t0 + row;
        if (tok < NT) {
            atomicAdd(&g_scratch[OFF_NORM2 + b * NT + tok], ra[row * 6]);
            float* dp = &g_scratch[OFF_DOTS + ((size_t)b * NT + tok) * NG];
#pragma unroll
            for (int j = 0; j < NG; j++) atomicAdd(dp + j, ra[row * 6 + 1 + j]);
        }
    }
}

// ---------------- softmax ----------------
__global__ void softmax_k(float* __restrict__ out) {
    int j = blockIdx.x, l = blockIdx.y, b = blockIdx.z;
    int f = threadIdx.x;
    __shared__ float red[8];
    float s = -1e30f;
    if (f < NF) {
        int t = l * NF + f;
        float n2 = g_scratch[OFF_NORM2 + b * NT + t];
        float d  = g_scratch[OFF_DOTS + ((size_t)b * NT + t) * NG + j];
        s = d * rsqrtf(n2 + L2EPS) * INV_ALPHA;
    }
    float m = s;
#pragma unroll
    for (int o = 16; o; o >>= 1) m = fmaxf(m, __shfl_xor_sync(0xffffffffu, m, o));
    if ((threadIdx.x & 31) == 0) red[threadIdx.x >> 5] = m;
    __syncthreads();
    m = red[0];
#pragma unroll
    for (int w = 1; w < 8; w++) m = fmaxf(m, red[w]);
    float e = (f < NF) ? expf(s - m) : 0.f;
    float sum = e;
#pragma unroll
    for (int o = 16; o; o >>= 1) sum += __shfl_xor_sync(0xffffffffu, sum, o);
    __syncthreads();
    if ((threadIdx.x & 31) == 0) red[threadIdx.x >> 5] = sum;
    __syncthreads();
    sum = 0.f;
#pragma unroll
    for (int w = 0; w < 8; w++) sum += red[w];
    if (f < NF)
        out[(((size_t)b * NL + l) * NG + j) * NF + f] = e / sum;
}

// ---------------------------------------------------------------------------
extern "C" void kernel_launch(void* const* d_in, const int* in_sizes, int n_in,
                              void* d_out, int out_size) {
    const float* gf = (const float*)d_in[0];
    const float* lf = (const float*)d_in[1];
    const float* Wq = (const float*)d_in[2];
    const float* Wk = (const float*)d_in[3];
    float* out = (float*)d_out;

    cudaFuncSetAttribute(gemm_mma_k, cudaFuncAttributeMaxDynamicSharedMemorySize,
                         GSMEM_BYTES);

    prep_k<<<(B * NT * (1 + NG) + 255) / 256, 256>>>(gf, Wk);
    convert_local_k<<<dim3(120, B), C>>>(lf);
    proj_k<<<dim3(NG + 2, B, 16), 256>>>(gf, Wq, Wk);
    meanghat_k<<<B, C>>>();
    gemm_mma_k<<<dim3(C / BN, (NT + BM - 1) / BM, B), 256, GSMEM_BYTES>>>();
    softmax_k<<<dim3(NG, NL, B), 256>>>(out);
}

// round 16
// speedup vs baseline: 1.6177x; 1.0370x over previous
#include <cuda_runtime.h>
#include <cuda_fp16.h>
#include <math.h>
#include <stdint.h>

#define B   8
#define NG  5
#define NL  75
#define NF  196
#define C   640
#define NT  (NL*NF)
#define NMEAN_DEN (NG + NT)
#define INV_ALPHA 10.0f
#define L2EPS 1e-12f

#define OFF_SG     0
#define OFF_SL     (OFF_SG + B*C)
#define OFF_GPROJ  (OFF_SL + B*C)
#define OFF_M1     (OFF_GPROJ + B*NG*C)
#define OFF_M2     (OFF_M1 + B*C)
#define OFF_MEAN   (OFF_M2 + B*C)
#define OFF_GHAT   (OFF_MEAN + B*C)
#define OFF_NORM2  (OFF_GHAT + B*NG*C)
#define OFF_DOTS   (OFF_NORM2 + B*NT)
#define SCRATCH_FLOATS (OFF_DOTS + B*NT*NG)

__device__ __align__(16) float g_scratch[SCRATCH_FLOATS];
__device__ __align__(16) __half g_lfh[(size_t)B * NT * C];   // 150.5 MB half copy
__device__ __align__(16) __half g_wkh[C * C];

// ---------------- helpers ----------------
__device__ __forceinline__ uint32_t smem_u32(const void* p) {
    uint32_t a;
    asm("{ .reg .u64 t; cvta.to.shared.u64 t, %1; cvt.u32.u64 %0, t; }" : "=r"(a) : "l"(p));
    return a;
}
__device__ __forceinline__ void cpa16(uint32_t dst, const void* src) {
    asm volatile("cp.async.cg.shared.global [%0], [%1], 16;" :: "r"(dst), "l"(src));
}
__device__ __forceinline__ void ldm_x4(uint32_t* r, uint32_t addr) {
    asm volatile("ldmatrix.sync.aligned.m8n8.x4.shared.b16 {%0,%1,%2,%3}, [%4];"
                 : "=r"(r[0]), "=r"(r[1]), "=r"(r[2]), "=r"(r[3]) : "r"(addr));
}
__device__ __forceinline__ void mma_f16(float* d, const uint32_t* a, const uint32_t* b) {
    asm volatile(
        "mma.sync.aligned.m16n8k16.row.col.f32.f16.f16.f32 "
        "{%0,%1,%2,%3}, {%4,%5,%6,%7}, {%8,%9}, {%0,%1,%2,%3};"
        : "+f"(d[0]), "+f"(d[1]), "+f"(d[2]), "+f"(d[3])
        : "r"(a[0]), "r"(a[1]), "r"(a[2]), "r"(a[3]), "r"(b[0]), "r"(b[1]));
}

// ---------------- merged prep: zero SL/NORM2/DOTS + sum_global + convert Wk ----
__global__ void prep_k(const float* __restrict__ gf, const float* __restrict__ Wk) {
    int i = blockIdx.x * blockDim.x + threadIdx.x;
    if (i < B * C) {
        g_scratch[OFF_SL + i] = 0.f;
        int b = i / C, c = i - b * C;
        float acc = 0.f;
#pragma unroll
        for (int g = 0; g < NG; g++) acc += gf[(b * NG + g) * C + c];
        g_scratch[OFF_SG + i] = acc;
    }
    if (i < C * C) g_wkh[i] = __float2half_rn(Wk[i]);
    if (i < B * NT * (1 + NG)) g_scratch[OFF_NORM2 + i] = 0.f;
}

// fused: SL column-sum + fp32->fp16 conversion of local_f
__global__ void convert_local_k(const float* __restrict__ lf) {
    int split = blockIdx.x, b = blockIdx.y, c = threadIdx.x;  // blockDim=640
    int per = (NT + gridDim.x - 1) / gridDim.x;
    int t0 = split * per, t1 = min(t0 + per, NT);
    const float* base = lf + ((size_t)b * NT) * C + c;
    __half* hbase = g_lfh + ((size_t)b * NT) * C + c;
    float acc = 0.f;
    for (int t = t0; t < t1; ++t) {
        float v = base[(size_t)t * C];
        acc += v;
        hbase[(size_t)t * C] = __float2half_rn(v);
    }
    atomicAdd(&g_scratch[OFF_SL + b * C + c], acc);
}

// coalesced warp-per-row projection; grid (NG+2, B, 16), 256 thr (40 dims/block)
__global__ void proj_k(const float* __restrict__ gf,
                       const float* __restrict__ Wq,
                       const float* __restrict__ Wk) {
    int r = blockIdx.x, b = blockIdx.y, ds = blockIdx.z;
    __shared__ float xs[C];
    const float* x; const float* W; float* out;
    if (r < NG)       { x = gf + (b * NG + r) * C;      W = Wq; out = &g_scratch[OFF_GPROJ + (b * NG + r) * C]; }
    else if (r == NG) { x = &g_scratch[OFF_SG + b * C]; W = Wq; out = &g_scratch[OFF_M1 + b * C]; }
    else              { x = &g_scratch[OFF_SL + b * C]; W = Wk; out = &g_scratch[OFF_M2 + b * C]; }
    for (int c = threadIdx.x; c < C; c += blockDim.x) xs[c] = x[c];
    __syncthreads();
    int w = threadIdx.x >> 5, lane = threadIdx.x & 31;
    for (int d = ds * 40 + w; d < (ds + 1) * 40; d += 8) {
        const float* wr = W + (size_t)d * C;
        float a = 0.f;
        for (int c = lane; c < C; c += 32) a += wr[c] * xs[c];
#pragma unroll
        for (int o = 16; o; o >>= 1) a += __shfl_xor_sync(0xffffffffu, a, o);
        if (lane == 0) out[d] = a;
    }
}

__global__ void meanghat_k() {
    int b = blockIdx.x, c = threadIdx.x;  // blockDim=640
    __shared__ float red[32];
    float mean = (g_scratch[OFF_M1 + b * C + c] + g_scratch[OFF_M2 + b * C + c])
                 * (1.0f / (float)NMEAN_DEN);
    g_scratch[OFF_MEAN + b * C + c] = mean;
    for (int j = 0; j < NG; j++) {
        float v = g_scratch[OFF_GPROJ + (b * NG + j) * C + c] - mean;
        float s = v * v;
#pragma unroll
        for (int o = 16; o; o >>= 1) s += __shfl_xor_sync(0xffffffffu, s, o);
        if ((threadIdx.x & 31) == 0) red[threadIdx.x >> 5] = s;
        __syncthreads();
        if (threadIdx.x < 32) {
            float t = (threadIdx.x < 20) ? red[threadIdx.x] : 0.f;
#pragma unroll
            for (int o = 16; o; o >>= 1) t += __shfl_xor_sync(0xffffffffu, t, o);
            if (threadIdx.x == 0) red[0] = t;
        }
        __syncthreads();
        float inv = rsqrtf(red[0] + L2EPS);
        g_scratch[OFF_GHAT + (b * NG + j) * C + c] = v * inv;
        __syncthreads();
    }
}

// ---------------- fp16 GEMM: 128x128x64, 3-stage, ONE sync per iter ----------
// 8 warps (2x4), warp tile 64x32. smem rows [row][72 halfs] (144B stride).
// eg/ra OVERLAY stage memory (dead after mainloop).
#define BM 128
#define BN 128
#define BK 64
#define ROWH 72
#define STAGE_BYTES (2*BM*ROWH*2)        // 36864
#define STG 3
#define GSMEM_BYTES (STG*STAGE_BYTES)    // 110592 ; 2 CTA/SM
#define EG_BOFF 0                        // overlay: eg[6][128] = 3072 B
#define RA_BOFF (6*BN*4)                 // overlay: ra[128][6] = 3072 B
#define KITER (C/BK)                     // 10

__device__ __forceinline__ void load_tile(int it, int stage, uint32_t sb,
                                          const __half* lfb, const __half* wkb,
                                          int t0, int d0, int tid) {
    uint32_t ab = sb + stage * STAGE_BYTES;
    uint32_t bb = ab + BM * ROWH * 2;
    int seg = tid & 7;            // 16B chunk within 128B data row
    int r0 = tid >> 3;            // 0..31
    int k0 = it * BK;
#pragma unroll
    for (int h = 0; h < 4; h++) {
        int row = r0 + h * 32;
        int tok = t0 + row; if (tok >= NT) tok = NT - 1;
        cpa16(ab + row * (ROWH * 2) + seg * 16, lfb + (size_t)tok * C + k0 + seg * 8);
        cpa16(bb + row * (ROWH * 2) + seg * 16, wkb + (size_t)(d0 + row) * C + k0 + seg * 8);
    }
    asm volatile("cp.async.commit_group;" ::: "memory");
}

__global__ __launch_bounds__(256, 2)
void gemm_mma_k() {
    extern __shared__ __align__(16) char smc[];
    uint32_t sb = smem_u32(smc);
    int tid = threadIdx.x, wid = tid >> 5, lane = tid & 31;
    int g = lane >> 2, t = lane & 3;
    int g8 = lane >> 3, lr = lane & 7;   // ldmatrix address groups
    int wm = wid >> 2, wn = wid & 3;     // 2 x 4 warp grid
    int chunk = blockIdx.x, b = blockIdx.z;
    int t0 = blockIdx.y * BM;
    int d0 = chunk * BN;
    const __half* lfb = g_lfh + (size_t)b * NT * C;

    float acc[4][4][4];
#pragma unroll
    for (int mt = 0; mt < 4; mt++)
#pragma unroll
        for (int nt = 0; nt < 4; nt++)
#pragma unroll
            for (int cc = 0; cc < 4; cc++) acc[mt][nt][cc] = 0.f;

    load_tile(0, 0, sb, lfb, g_wkh, t0, d0, tid);
    load_tile(1, 1, sb, lfb, g_wkh, t0, d0, tid);

    int a_row = wm * 64 + (g8 & 1) * 8 + lr;     // + mt*16 ; kcol = (g8>>1)*8
    int a_kc8 = (g8 >> 1) * 8;
    int b_row = wn * 32 + g8 * 8 + lr;           // all 4 n8-tiles

    for (int it = 0; it < KITER; it++) {
        int s = it % STG;
        if (it == KITER - 1) asm volatile("cp.async.wait_group 0;" ::: "memory");
        else                 asm volatile("cp.async.wait_group 1;" ::: "memory");
        __syncthreads();   // single barrier per iteration (3-stage safety)

        uint32_t as_ = sb + s * STAGE_BYTES;
        uint32_t bs_ = as_ + BM * ROWH * 2;
#pragma unroll
        for (int kk = 0; kk < 4; kk++) {
            int kb = kk * 16;
            uint32_t af[4][4], bt0[4], bt1[4];
#pragma unroll
            for (int mt = 0; mt < 4; mt++)
                ldm_x4(af[mt], as_ + ((a_row + mt * 16) * ROWH + kb + a_kc8) * 2);
            ldm_x4(bt0, bs_ + (b_row * ROWH + kb) * 2);
            ldm_x4(bt1, bs_ + (b_row * ROWH + kb + 8) * 2);
#pragma unroll
            for (int mt = 0; mt < 4; mt++)
#pragma unroll
                for (int nt = 0; nt < 4; nt++) {
                    uint32_t bf[2] = {bt0[nt], bt1[nt]};
                    mma_f16(acc[mt][nt], af[mt], bf);
                }
        }
        // prefetch it+2 into stage (it+2)%3 — its last readers (iter it-1)
        // all passed the sync at the top of this iteration.
        if (it + 2 < KITER) load_tile(it + 2, (it + 2) % STG, sb, lfb, g_wkh, t0, d0, tid);
    }
    __syncthreads();   // all reads of stage memory done before eg/ra overlay

    // ---- epilogue (eg/ra overlay stage smem) ----
    float* eg = (float*)(smc + EG_BOFF);   // eg[j][128], j=0..4 ghat, j=5 mean
    float* ra = (float*)(smc + RA_BOFF);   // rowacc[128][6]
    for (int idx = tid; idx < 6 * BN; idx += 256) {
        int j = idx >> 7, c = idx & 127;
        eg[idx] = (j < 5) ? g_scratch[OFF_GHAT + (b * NG + j) * C + d0 + c]
                          : g_scratch[OFF_MEAN + b * C + d0 + c];
    }
    for (int idx = tid; idx < BM * 6; idx += 256) ra[RA_BOFF ? idx : idx] = 0.f;
    __syncthreads();

#pragma unroll
    for (int mt = 0; mt < 4; mt++) {
#pragma unroll
        for (int rv = 0; rv < 2; rv++) {
            int row = wm * 64 + mt * 16 + g + rv * 8;
            float v[6] = {0.f, 0.f, 0.f, 0.f, 0.f, 0.f};
#pragma unroll
            for (int nt = 0; nt < 4; nt++) {
#pragma unroll
                for (int cc = 0; cc < 2; cc++) {
                    int col = wn * 32 + nt * 8 + 2 * t + cc;
                    float z = acc[mt][nt][rv * 2 + cc] - eg[5 * BN + col];
                    v[0] = fmaf(z, z, v[0]);
#pragma unroll
                    for (int j = 0; j < NG; j++)
                        v[1 + j] = fmaf(z, eg[j * BN + col], v[1 + j]);
                }
            }
#pragma unroll
            for (int j = 0; j < 6; j++) {
                v[j] += __shfl_xor_sync(0xffffffffu, v[j], 1);
                v[j] += __shfl_xor_sync(0xffffffffu, v[j], 2);
            }
            if (t == 0) {
#pragma unroll
                for (int j = 0; j < 6; j++) atomicAdd(&ra[row * 6 + j], v[j]);
            }
        }
    }
    __syncthreads();

    for (int row = tid; row < BM; row += 256) {
        int tok = t0 + row;
        if (tok < NT) {
            atomicAdd(&g_scratch[OFF_NORM2 + b * NT + tok], ra[row * 6]);
            float* dp = &g_scratch[OFF_DOTS + ((size_t)b * NT + tok) * NG];
#pragma unroll
            for (int j = 0; j < NG; j++) atomicAdd(dp + j, ra[row * 6 + 1 + j]);
        }
    }
}

// ---------------- softmax ----------------
__global__ void softmax_k(float* __restrict__ out) {
    int j = blockIdx.x, l = blockIdx.y, b = blockIdx.z;
    int f = threadIdx.x;
    __shared__ float red[8];
    float s = -1e30f;
    if (f < NF) {
        int t = l * NF + f;
        float n2 = g_scratch[OFF_NORM2 + b * NT + t];
        float d  = g_scratch[OFF_DOTS + ((size_t)b * NT + t) * NG + j];
        s = d * rsqrtf(n2 + L2EPS) * INV_ALPHA;
    }
    float m = s;
#pragma unroll
    for (int o = 16; o; o >>= 1) m = fmaxf(m, __shfl_xor_sync(0xffffffffu, m, o));
    if ((threadIdx.x & 31) == 0) red[threadIdx.x >> 5] = m;
    __syncthreads();
    m = red[0];
#pragma unroll
    for (int w = 1; w < 8; w++) m = fmaxf(m, red[w]);
    float e = (f < NF) ? expf(s - m) : 0.f;
    float sum = e;
#pragma unroll
    for (int o = 16; o; o >>= 1) sum += __shfl_xor_sync(0xffffffffu, sum, o);
    __syncthreads();
    if ((threadIdx.x & 31) == 0) red[threadIdx.x >> 5] = sum;
    __syncthreads();
    sum = 0.f;
#pragma unroll
    for (int w = 0; w < 8; w++) sum += red[w];
    if (f < NF)
        out[(((size_t)b * NL + l) * NG + j) * NF + f] = e / sum;
}

// ---------------------------------------------------------------------------
extern "C" void kernel_launch(void* const* d_in, const int* in_sizes, int n_in,
                              void* d_out, int out_size) {
    const float* gf = (const float*)d_in[0];
    const float* lf = (const float*)d_in[1];
    const float* Wq = (const float*)d_in[2];
    const float* Wk = (const float*)d_in[3];
    float* out = (float*)d_out;

    cudaFuncSetAttribute(gemm_mma_k, cudaFuncAttributeMaxDynamicSharedMemorySize,
                         GSMEM_BYTES);

    prep_k<<<(B * NT * (1 + NG) + 255) / 256, 256>>>(gf, Wk);
    convert_local_k<<<dim3(120, B), C>>>(lf);
    proj_k<<<dim3(NG + 2, B, 16), 256>>>(gf, Wq, Wk);
    meanghat_k<<<B, C>>>();
    gemm_mma_k<<<dim3(C / BN, (NT + BM - 1) / BM, B), 256, GSMEM_BYTES>>>();
    softmax_k<<<dim3(NG, NL, B), 256>>>(out);
}